// round 2
// baseline (speedup 1.0000x reference)
#include <cuda_runtime.h>

#define NN 50000
#define EE 800000
#define ET (EE + NN)          // edges + self-loops = 850000
#define HEADS 8
#define CH 32
#define INF 256
#define OUTF 256
#define NEG 0.2f
#define LNEPS 1e-5f

// ---------------- scratch (device globals: no allocation allowed) ------------
__device__ float g_h[(size_t)NN * OUTF];        // x @ W           (51.2 MB)
__device__ float g_asrc[NN * HEADS];
__device__ float g_adst[NN * HEADS];
__device__ float g_emax[NN * HEADS];
__device__ float g_denom[NN * HEADS];
__device__ float g_ex[(size_t)ET * HEADS];      // per-edge exp    (27.2 MB)

// ---------------- GEMM: h = x @ W  (64x64 tile, 256 thr, 4x4 micro) ----------
__global__ void gemm_kernel(const float* __restrict__ X, const float* __restrict__ W) {
    __shared__ float As[64][20];   // row-major, padded (float4-aligned: 20*4=80B)
    __shared__ float Bs[16][68];   // padded       (68*4=272B, 16B aligned)

    int tid = threadIdx.x;
    int tx = tid & 15, ty = tid >> 4;
    int row0 = blockIdx.x * 64;
    int col0 = blockIdx.y * 64;

    int lm  = tid >> 2;   // 0..63 (A row in tile)
    int lkq = tid & 3;    // 0..3  (A k quad)
    int lk  = tid >> 4;   // 0..15 (B k)
    int lcq = tid & 15;   // 0..15 (B col quad)

    float acc[4][4] = {};

    for (int k0 = 0; k0 < INF; k0 += 16) {
        float4 av = make_float4(0.f, 0.f, 0.f, 0.f);
        int arow = row0 + lm;
        if (arow < NN)
            av = *(const float4*)&X[(size_t)arow * INF + k0 + lkq * 4];
        *(float4*)&As[lm][lkq * 4] = av;

        float4 bv = *(const float4*)&W[(size_t)(k0 + lk) * OUTF + col0 + lcq * 4];
        *(float4*)&Bs[lk][lcq * 4] = bv;
        __syncthreads();

        #pragma unroll
        for (int k = 0; k < 16; k++) {
            float a0 = As[ty * 4 + 0][k];
            float a1 = As[ty * 4 + 1][k];
            float a2 = As[ty * 4 + 2][k];
            float a3 = As[ty * 4 + 3][k];
            float4 b = *(const float4*)&Bs[k][tx * 4];
            acc[0][0] += a0 * b.x; acc[0][1] += a0 * b.y; acc[0][2] += a0 * b.z; acc[0][3] += a0 * b.w;
            acc[1][0] += a1 * b.x; acc[1][1] += a1 * b.y; acc[1][2] += a1 * b.z; acc[1][3] += a1 * b.w;
            acc[2][0] += a2 * b.x; acc[2][1] += a2 * b.y; acc[2][2] += a2 * b.z; acc[2][3] += a2 * b.w;
            acc[3][0] += a3 * b.x; acc[3][1] += a3 * b.y; acc[3][2] += a3 * b.z; acc[3][3] += a3 * b.w;
        }
        __syncthreads();
    }

    #pragma unroll
    for (int i = 0; i < 4; i++) {
        int r = row0 + ty * 4 + i;
        if (r < NN) {
            float4 v = make_float4(acc[i][0], acc[i][1], acc[i][2], acc[i][3]);
            *(float4*)&g_h[(size_t)r * OUTF + col0 + tx * 4] = v;
        }
    }
}

// ---------------- per-node attention coefficients ---------------------------
__global__ void att_kernel(const float* __restrict__ att_src,
                           const float* __restrict__ att_dst) {
    int n = blockIdx.x;
    int w = threadIdx.x >> 5, lane = threadIdx.x & 31;   // warp w == head w
    float hv = g_h[(size_t)n * OUTF + w * 32 + lane];
    float s = hv * att_src[w * 32 + lane];
    float d = hv * att_dst[w * 32 + lane];
    #pragma unroll
    for (int o = 16; o; o >>= 1) {
        s += __shfl_down_sync(0xffffffffu, s, o);
        d += __shfl_down_sync(0xffffffffu, d, o);
    }
    if (lane == 0) {
        g_asrc[n * HEADS + w] = s;
        g_adst[n * HEADS + w] = d;
    }
}

// ---------------- init out / emax / denom -----------------------------------
__global__ void init_kernel(float* __restrict__ out) {
    int i = blockIdx.x * blockDim.x + threadIdx.x;
    if (i < NN * OUTF) out[i] = 0.f;
    if (i < NN * HEADS) {
        g_emax[i] = __int_as_float(0xff800000);  // -inf
        g_denom[i] = 0.f;
    }
}

// dual-representation single-atomic float max (init must be -inf)
__device__ __forceinline__ void atomicMaxF(float* addr, float v) {
    if (v >= 0.f) atomicMax((int*)addr, __float_as_int(v));
    else          atomicMin((unsigned int*)addr, (unsigned int)__float_as_int(v));
}

// edge_index is int32 on device (JAX default x64-disabled downcasts int64)
__device__ __forceinline__ void edge_sd(int e, const int* __restrict__ ei,
                                        int& s, int& d) {
    if (e < EE) { s = ei[e]; d = ei[EE + e]; }
    else        { s = d = e - EE; }      // self-loop
}

// ---------------- edge pass 1: segment max ----------------------------------
__global__ void emax_kernel(const int* __restrict__ ei) {
    int t = blockIdx.x * blockDim.x + threadIdx.x;
    if (t >= ET * HEADS) return;
    int e = t >> 3, hd = t & 7;
    int s, d; edge_sd(e, ei, s, d);
    float v = g_asrc[s * HEADS + hd] + g_adst[d * HEADS + hd];
    v = v > 0.f ? v : NEG * v;
    atomicMaxF(&g_emax[d * HEADS + hd], v);
}

// ---------------- edge pass 2: exp + segment sum ----------------------------
__global__ void expsum_kernel(const int* __restrict__ ei) {
    int t = blockIdx.x * blockDim.x + threadIdx.x;
    if (t >= ET * HEADS) return;
    int e = t >> 3, hd = t & 7;
    int s, d; edge_sd(e, ei, s, d);
    float v = g_asrc[s * HEADS + hd] + g_adst[d * HEADS + hd];
    v = v > 0.f ? v : NEG * v;
    float ex = __expf(v - g_emax[d * HEADS + hd]);
    g_ex[(size_t)e * HEADS + hd] = ex;
    atomicAdd(&g_denom[d * HEADS + hd], ex);
}

// ---------------- edge pass 3: alpha-weighted aggregate (warp per edge) -----
__global__ void aggregate_kernel(const int* __restrict__ ei,
                                 float* __restrict__ out) {
    int gw = (blockIdx.x * blockDim.x + threadIdx.x) >> 5;
    int lane = threadIdx.x & 31;
    if (gw >= ET) return;
    int s, d; edge_sd(gw, ei, s, d);

    float al = 0.f;
    if (lane < HEADS)
        al = g_ex[(size_t)gw * HEADS + lane] / g_denom[d * HEADS + lane];

    const float* hs = &g_h[(size_t)s * OUTF];
    float*       od = &out[(size_t)d * OUTF];
    #pragma unroll
    for (int k = 0; k < HEADS; k++) {
        float a = __shfl_sync(0xffffffffu, al, k);
        atomicAdd(&od[k * 32 + lane], hs[k * 32 + lane] * a);
    }
}

// ---------------- LayerNorm + ReLU (in-place on out) ------------------------
__global__ void ln_kernel(float* __restrict__ out, const float* __restrict__ bias,
                          const float* __restrict__ gamma, const float* __restrict__ beta) {
    int n = blockIdx.x;
    int c = threadIdx.x;
    float v = out[(size_t)n * OUTF + c] + bias[c];

    __shared__ float ssum[8], ssq[8];
    float s = v, q = v * v;
    #pragma unroll
    for (int o = 16; o; o >>= 1) {
        s += __shfl_down_sync(0xffffffffu, s, o);
        q += __shfl_down_sync(0xffffffffu, q, o);
    }
    int w = c >> 5, lane = c & 31;
    if (lane == 0) { ssum[w] = s; ssq[w] = q; }
    __syncthreads();

    __shared__ float mean_s, rstd_s;
    if (c == 0) {
        float S = 0.f, Q = 0.f;
        #pragma unroll
        for (int i = 0; i < 8; i++) { S += ssum[i]; Q += ssq[i]; }
        float mu = S * (1.f / OUTF);
        float var = Q * (1.f / OUTF) - mu * mu;
        mean_s = mu;
        rstd_s = rsqrtf(var + LNEPS);
    }
    __syncthreads();

    float y = (v - mean_s) * rstd_s * gamma[c] + beta[c];
    out[(size_t)n * OUTF + c] = fmaxf(y, 0.f);
}

// ---------------- launch -----------------------------------------------------
extern "C" void kernel_launch(void* const* d_in, const int* in_sizes, int n_in,
                              void* d_out, int out_size) {
    const float* x       = (const float*)d_in[0];
    const int*   ei      = (const int*)d_in[1];
    const float* W       = (const float*)d_in[2];
    const float* att_src = (const float*)d_in[3];
    const float* att_dst = (const float*)d_in[4];
    const float* bias    = (const float*)d_in[5];
    const float* gamma   = (const float*)d_in[6];
    const float* beta    = (const float*)d_in[7];
    float* out = (float*)d_out;

    dim3 gg((NN + 63) / 64, OUTF / 64);
    gemm_kernel<<<gg, 256>>>(x, W);
    att_kernel<<<NN, 256>>>(att_src, att_dst);
    init_kernel<<<(NN * OUTF + 255) / 256, 256>>>(out);
    emax_kernel<<<(ET * HEADS + 255) / 256, 256>>>(ei);
    expsum_kernel<<<(ET * HEADS + 255) / 256, 256>>>(ei);
    aggregate_kernel<<<((size_t)ET * 32 + 255) / 256, 256>>>(ei, out);
    ln_kernel<<<NN, 256>>>(out, bias, gamma, beta);
}

// round 3
// speedup vs baseline: 1.3508x; 1.3508x over previous
#include <cuda_runtime.h>

#define NN 50000
#define EE 800000
#define ET (EE + NN)          // edges + self-loops = 850000
#define HEADS 8
#define CH 32
#define INF 256
#define OUTF 256
#define NEG 0.2f
#define LNEPS 1e-5f

// ---------------- scratch (device globals: no allocation allowed) ------------
__device__ float g_h[(size_t)NN * OUTF];        // x @ W           (51.2 MB)
__device__ float g_asrc[NN * HEADS];
__device__ float g_adst[NN * HEADS];
__device__ float g_denom[NN * HEADS];
__device__ float g_ex[(size_t)ET * HEADS];      // per-edge exp    (27.2 MB)

// vectorized global float4 reduction (sm_90+)
__device__ __forceinline__ void red4(float4* addr, float4 v) {
    asm volatile("red.global.add.v4.f32 [%0], {%1,%2,%3,%4};"
                 :: "l"(addr), "f"(v.x), "f"(v.y), "f"(v.z), "f"(v.w) : "memory");
}

// ---------------- GEMM: h = x @ W  (64x64 tile, 256 thr, 4x4 micro) ----------
__global__ void gemm_kernel(const float* __restrict__ X, const float* __restrict__ W) {
    __shared__ float As[64][20];
    __shared__ float Bs[16][68];

    int tid = threadIdx.x;
    int tx = tid & 15, ty = tid >> 4;
    int row0 = blockIdx.x * 64;
    int col0 = blockIdx.y * 64;

    int lm  = tid >> 2;   // 0..63 (A row in tile)
    int lkq = tid & 3;    // 0..3  (A k quad)
    int lk  = tid >> 4;   // 0..15 (B k)
    int lcq = tid & 15;   // 0..15 (B col quad)

    float acc[4][4] = {};

    for (int k0 = 0; k0 < INF; k0 += 16) {
        float4 av = make_float4(0.f, 0.f, 0.f, 0.f);
        int arow = row0 + lm;
        if (arow < NN)
            av = *(const float4*)&X[(size_t)arow * INF + k0 + lkq * 4];
        *(float4*)&As[lm][lkq * 4] = av;

        float4 bv = *(const float4*)&W[(size_t)(k0 + lk) * OUTF + col0 + lcq * 4];
        *(float4*)&Bs[lk][lcq * 4] = bv;
        __syncthreads();

        #pragma unroll
        for (int k = 0; k < 16; k++) {
            float a0 = As[ty * 4 + 0][k];
            float a1 = As[ty * 4 + 1][k];
            float a2 = As[ty * 4 + 2][k];
            float a3 = As[ty * 4 + 3][k];
            float4 b = *(const float4*)&Bs[k][tx * 4];
            acc[0][0] += a0 * b.x; acc[0][1] += a0 * b.y; acc[0][2] += a0 * b.z; acc[0][3] += a0 * b.w;
            acc[1][0] += a1 * b.x; acc[1][1] += a1 * b.y; acc[1][2] += a1 * b.z; acc[1][3] += a1 * b.w;
            acc[2][0] += a2 * b.x; acc[2][1] += a2 * b.y; acc[2][2] += a2 * b.z; acc[2][3] += a2 * b.w;
            acc[3][0] += a3 * b.x; acc[3][1] += a3 * b.y; acc[3][2] += a3 * b.z; acc[3][3] += a3 * b.w;
        }
        __syncthreads();
    }

    #pragma unroll
    for (int i = 0; i < 4; i++) {
        int r = row0 + ty * 4 + i;
        if (r < NN) {
            float4 v = make_float4(acc[i][0], acc[i][1], acc[i][2], acc[i][3]);
            *(float4*)&g_h[(size_t)r * OUTF + col0 + tx * 4] = v;
        }
    }
}

// ---------------- per-node attention coefficients ---------------------------
__global__ void att_kernel(const float* __restrict__ att_src,
                           const float* __restrict__ att_dst) {
    int n = blockIdx.x;
    int w = threadIdx.x >> 5, lane = threadIdx.x & 31;   // warp w == head w
    float hv = g_h[(size_t)n * OUTF + w * 32 + lane];
    float s = hv * att_src[w * 32 + lane];
    float d = hv * att_dst[w * 32 + lane];
    #pragma unroll
    for (int o = 16; o; o >>= 1) {
        s += __shfl_down_sync(0xffffffffu, s, o);
        d += __shfl_down_sync(0xffffffffu, d, o);
    }
    if (lane == 0) {
        g_asrc[n * HEADS + w] = s;
        g_adst[n * HEADS + w] = d;
    }
}

// ---------------- init out / denom ------------------------------------------
__global__ void init_kernel(float* __restrict__ out) {
    int i = blockIdx.x * blockDim.x + threadIdx.x;
    if (i < NN * OUTF) out[i] = 0.f;
    if (i < NN * HEADS) g_denom[i] = 0.f;
}

// edge_index is int32 on device (JAX x64-disabled downcasts int64)
__device__ __forceinline__ void edge_sd(int e, const int* __restrict__ ei,
                                        int& s, int& d) {
    if (e < EE) { s = ei[e]; d = ei[EE + e]; }
    else        { s = d = e - EE; }      // self-loop
}

// ---------------- edge pass 1: exp + segment sum (no max needed; e <~ 8) ----
__global__ void edgeexp_kernel(const int* __restrict__ ei) {
    int e = blockIdx.x * blockDim.x + threadIdx.x;
    if (e >= ET) return;
    int s, d; edge_sd(e, ei, s, d);

    float4 s0 = *(const float4*)&g_asrc[s * HEADS];
    float4 s1 = *(const float4*)&g_asrc[s * HEADS + 4];
    float4 d0 = *(const float4*)&g_adst[d * HEADS];
    float4 d1 = *(const float4*)&g_adst[d * HEADS + 4];

    float v[8] = { s0.x + d0.x, s0.y + d0.y, s0.z + d0.z, s0.w + d0.w,
                   s1.x + d1.x, s1.y + d1.y, s1.z + d1.z, s1.w + d1.w };
    float ex[8];
    #pragma unroll
    for (int i = 0; i < 8; i++) {
        float t = v[i] > 0.f ? v[i] : NEG * v[i];
        ex[i] = __expf(t);
    }
    float4 e0 = make_float4(ex[0], ex[1], ex[2], ex[3]);
    float4 e1 = make_float4(ex[4], ex[5], ex[6], ex[7]);
    *(float4*)&g_ex[(size_t)e * HEADS]     = e0;
    *(float4*)&g_ex[(size_t)e * HEADS + 4] = e1;
    red4((float4*)&g_denom[d * HEADS],     e0);
    red4((float4*)&g_denom[d * HEADS + 4], e1);
}

// ---------------- edge pass 2: alpha-weighted aggregate (warp per edge) -----
__global__ void aggregate_kernel(const int* __restrict__ ei,
                                 float* __restrict__ out) {
    int gw = (blockIdx.x * blockDim.x + threadIdx.x) >> 5;
    int lane = threadIdx.x & 31;
    if (gw >= ET) return;
    int s, d; edge_sd(gw, ei, s, d);

    float al = 0.f;
    if (lane < HEADS)
        al = g_ex[(size_t)gw * HEADS + lane] / g_denom[d * HEADS + lane];

    // lane i covers cols [4i,4i+4) and [128+4i,128+4i+4); head = col/32
    float a0 = __shfl_sync(0xffffffffu, al, lane >> 3);
    float a1 = __shfl_sync(0xffffffffu, al, 4 + (lane >> 3));

    const float4* hs = (const float4*)&g_h[(size_t)s * OUTF];
    float4*       od = (float4*)&out[(size_t)d * OUTF];

    float4 h0 = hs[lane];
    float4 h1 = hs[32 + lane];
    h0.x *= a0; h0.y *= a0; h0.z *= a0; h0.w *= a0;
    h1.x *= a1; h1.y *= a1; h1.z *= a1; h1.w *= a1;
    red4(&od[lane],      h0);
    red4(&od[32 + lane], h1);
}

// ---------------- LayerNorm + ReLU (in-place on out) ------------------------
__global__ void ln_kernel(float* __restrict__ out, const float* __restrict__ bias,
                          const float* __restrict__ gamma, const float* __restrict__ beta) {
    int n = blockIdx.x;
    int c = threadIdx.x;
    float v = out[(size_t)n * OUTF + c] + bias[c];

    __shared__ float ssum[8], ssq[8];
    float s = v, q = v * v;
    #pragma unroll
    for (int o = 16; o; o >>= 1) {
        s += __shfl_down_sync(0xffffffffu, s, o);
        q += __shfl_down_sync(0xffffffffu, q, o);
    }
    int w = c >> 5, lane = c & 31;
    if (lane == 0) { ssum[w] = s; ssq[w] = q; }
    __syncthreads();

    __shared__ float mean_s, rstd_s;
    if (c == 0) {
        float S = 0.f, Q = 0.f;
        #pragma unroll
        for (int i = 0; i < 8; i++) { S += ssum[i]; Q += ssq[i]; }
        float mu = S * (1.f / OUTF);
        float var = Q * (1.f / OUTF) - mu * mu;
        mean_s = mu;
        rstd_s = rsqrtf(var + LNEPS);
    }
    __syncthreads();

    float y = (v - mean_s) * rstd_s * gamma[c] + beta[c];
    out[(size_t)n * OUTF + c] = fmaxf(y, 0.f);
}

// ---------------- launch -----------------------------------------------------
extern "C" void kernel_launch(void* const* d_in, const int* in_sizes, int n_in,
                              void* d_out, int out_size) {
    const float* x       = (const float*)d_in[0];
    const int*   ei      = (const int*)d_in[1];
    const float* W       = (const float*)d_in[2];
    const float* att_src = (const float*)d_in[3];
    const float* att_dst = (const float*)d_in[4];
    const float* bias    = (const float*)d_in[5];
    const float* gamma   = (const float*)d_in[6];
    const float* beta    = (const float*)d_in[7];
    float* out = (float*)d_out;

    dim3 gg((NN + 63) / 64, OUTF / 64);
    gemm_kernel<<<gg, 256>>>(x, W);
    att_kernel<<<NN, 256>>>(att_src, att_dst);
    init_kernel<<<(NN * OUTF + 255) / 256, 256>>>(out);
    edgeexp_kernel<<<(ET + 255) / 256, 256>>>(ei);
    aggregate_kernel<<<((size_t)ET * 32 + 255) / 256, 256>>>(ei, out);
    ln_kernel<<<NN, 256>>>(out, bias, gamma, beta);
}

// round 4
// speedup vs baseline: 1.3690x; 1.0135x over previous
#include <cuda_runtime.h>

#define NN 50000
#define EE 800000
#define ET (EE + NN)          // edges + self-loops = 850000
#define HEADS 8
#define CH 32
#define INF 256
#define OUTF 256
#define NEG 0.2f
#define LNEPS 1e-5f

// ---------------- scratch (device globals) -----------------------------------
__device__ float g_h[(size_t)NN * OUTF];        // x @ W  (51.2 MB, L2-resident)
__device__ float g_asrc[NN * HEADS];
__device__ float g_adst[NN * HEADS];
__device__ int   g_deg[NN];
__device__ int   g_start[NN + 1];
__device__ int   g_cursor[NN];
__device__ int   g_csr[ET];                     // edge ids bucketed by dst

// ---------------- GEMM: h = x @ W  (64x64 tile, FFMA2 micro-kernel) ----------
__global__ void gemm_kernel(const float* __restrict__ X, const float* __restrict__ W) {
    __shared__ float As[64][20];
    __shared__ float Bs[16][68];

    int tid = threadIdx.x;
    int tx = tid & 15, ty = tid >> 4;
    int row0 = blockIdx.x * 64;
    int col0 = blockIdx.y * 64;

    int lm  = tid >> 2;   // 0..63 (A row in tile)
    int lkq = tid & 3;    // 0..3  (A k quad)
    int lk  = tid >> 4;   // 0..15 (B k)
    int lcq = tid & 15;   // 0..15 (B col quad)

    // acc[i][p]: row i, column pair p (2 fp32 packed in b64)
    unsigned long long acc[4][2] = {};

    for (int k0 = 0; k0 < INF; k0 += 16) {
        float4 av = make_float4(0.f, 0.f, 0.f, 0.f);
        int arow = row0 + lm;
        if (arow < NN)
            av = *(const float4*)&X[(size_t)arow * INF + k0 + lkq * 4];
        *(float4*)&As[lm][lkq * 4] = av;

        float4 bv = *(const float4*)&W[(size_t)(k0 + lk) * OUTF + col0 + lcq * 4];
        *(float4*)&Bs[lk][lcq * 4] = bv;
        __syncthreads();

        #pragma unroll
        for (int k = 0; k < 16; k++) {
            // b column pair loads (16B-aligned in smem)
            unsigned long long b01 = *(const unsigned long long*)&Bs[k][tx * 4];
            unsigned long long b23 = *(const unsigned long long*)&Bs[k][tx * 4 + 2];
            #pragma unroll
            for (int i = 0; i < 4; i++) {
                float a = As[ty * 4 + i][k];
                unsigned long long ad;
                asm("mov.b64 %0, {%1, %1};" : "=l"(ad) : "f"(a));
                asm("fma.rn.f32x2 %0, %1, %2, %0;" : "+l"(acc[i][0]) : "l"(ad), "l"(b01));
                asm("fma.rn.f32x2 %0, %1, %2, %0;" : "+l"(acc[i][1]) : "l"(ad), "l"(b23));
            }
        }
        __syncthreads();
    }

    #pragma unroll
    for (int i = 0; i < 4; i++) {
        int r = row0 + ty * 4 + i;
        if (r < NN) {
            float4 v;
            asm("mov.b64 {%0, %1}, %2;" : "=f"(v.x), "=f"(v.y) : "l"(acc[i][0]));
            asm("mov.b64 {%0, %1}, %2;" : "=f"(v.z), "=f"(v.w) : "l"(acc[i][1]));
            *(float4*)&g_h[(size_t)r * OUTF + col0 + tx * 4] = v;
        }
    }
}

// ---------------- per-node attention coefficients ---------------------------
__global__ void att_kernel(const float* __restrict__ att_src,
                           const float* __restrict__ att_dst) {
    int n = blockIdx.x;
    int w = threadIdx.x >> 5, lane = threadIdx.x & 31;   // warp w == head w
    float hv = g_h[(size_t)n * OUTF + w * 32 + lane];
    float s = hv * att_src[w * 32 + lane];
    float d = hv * att_dst[w * 32 + lane];
    #pragma unroll
    for (int o = 16; o; o >>= 1) {
        s += __shfl_down_sync(0xffffffffu, s, o);
        d += __shfl_down_sync(0xffffffffu, d, o);
    }
    if (lane == 0) {
        g_asrc[n * HEADS + w] = s;
        g_adst[n * HEADS + w] = d;
    }
}

// ---------------- CSR build --------------------------------------------------
__global__ void zero_deg_kernel() {
    int i = blockIdx.x * blockDim.x + threadIdx.x;
    if (i < NN) g_deg[i] = 0;
}

__global__ void count_kernel(const int* __restrict__ ei) {
    int e = blockIdx.x * blockDim.x + threadIdx.x;
    if (e >= ET) return;
    int d = (e < EE) ? ei[EE + e] : e - EE;
    atomicAdd(&g_deg[d], 1);
}

// single-block exclusive scan over g_deg -> g_start / g_cursor
__global__ void scan_kernel() {
    int tid = threadIdx.x;
    int lane = tid & 31, w = tid >> 5;
    __shared__ int wsum[32];
    __shared__ int s_run;
    if (tid == 0) s_run = 0;
    __syncthreads();

    for (int base = 0; base < NN; base += 1024) {
        int i = base + tid;
        int v = (i < NN) ? g_deg[i] : 0;
        int x = v;
        #pragma unroll
        for (int o = 1; o < 32; o <<= 1) {
            int y = __shfl_up_sync(0xffffffffu, x, o);
            if (lane >= o) x += y;
        }
        if (lane == 31) wsum[w] = x;
        __syncthreads();
        if (w == 0) {
            int y = wsum[lane];
            #pragma unroll
            for (int o = 1; o < 32; o <<= 1) {
                int z = __shfl_up_sync(0xffffffffu, y, o);
                if (lane >= o) y += z;
            }
            wsum[lane] = y;
        }
        __syncthreads();
        int incl = x + (w > 0 ? wsum[w - 1] : 0) + s_run;
        if (i < NN) {
            g_start[i] = incl - v;
            g_cursor[i] = incl - v;
        }
        __syncthreads();
        if (tid == 1023) s_run = incl;
        __syncthreads();
    }
    if (threadIdx.x == 0) g_start[NN] = s_run;
}

__global__ void fill_kernel(const int* __restrict__ ei) {
    int e = blockIdx.x * blockDim.x + threadIdx.x;
    if (e >= ET) return;
    int d = (e < EE) ? ei[EE + e] : e - EE;
    int pos = atomicAdd(&g_cursor[d], 1);
    g_csr[pos] = e;
}

// ---------------- fused aggregate + softmax + bias + LN + ReLU ---------------
__global__ void agg_ln_kernel(const int* __restrict__ ei, float* __restrict__ out,
                              const float* __restrict__ bias,
                              const float* __restrict__ gamma,
                              const float* __restrict__ beta) {
    int d = blockIdx.x;                 // dst node
    int c = threadIdx.x;                // output column 0..255
    int head = c >> 5, lane = c & 31;

    int beg = g_start[d], end = g_start[d + 1];
    float adst_h = g_adst[d * HEADS + head];

    float acc = 0.f, den = 0.f;
    __shared__ int s_src[64];

    for (int base = beg; base < end; base += 64) {
        int nb = min(64, end - base);
        if (c < nb) {
            int eid = g_csr[base + c];
            s_src[c] = (eid < EE) ? ei[eid] : eid - EE;
        }
        __syncthreads();
        #pragma unroll 2
        for (int j = 0; j < nb; j++) {
            int src = s_src[j];
            float e = g_asrc[src * HEADS + head] + adst_h;  // warp-uniform
            e = e > 0.f ? e : NEG * e;
            float ex = __expf(e);
            den += ex;
            acc += ex * g_h[(size_t)src * OUTF + c];
        }
        __syncthreads();
    }

    float v = acc / den + bias[c];      // den > 0 (self-loop guarantees deg>=1)

    // LayerNorm over 256 + ReLU
    __shared__ float ssum[8], ssq[8];
    float s = v, q = v * v;
    #pragma unroll
    for (int o = 16; o; o >>= 1) {
        s += __shfl_down_sync(0xffffffffu, s, o);
        q += __shfl_down_sync(0xffffffffu, q, o);
    }
    if (lane == 0) { ssum[head] = s; ssq[head] = q; }
    __syncthreads();

    __shared__ float mean_s, rstd_s;
    if (c == 0) {
        float S = 0.f, Q = 0.f;
        #pragma unroll
        for (int i = 0; i < 8; i++) { S += ssum[i]; Q += ssq[i]; }
        float mu = S * (1.f / OUTF);
        float var = Q * (1.f / OUTF) - mu * mu;
        mean_s = mu;
        rstd_s = rsqrtf(var + LNEPS);
    }
    __syncthreads();

    float y = (v - mean_s) * rstd_s * gamma[c] + beta[c];
    out[(size_t)d * OUTF + c] = fmaxf(y, 0.f);
}

// ---------------- launch -----------------------------------------------------
extern "C" void kernel_launch(void* const* d_in, const int* in_sizes, int n_in,
                              void* d_out, int out_size) {
    const float* x       = (const float*)d_in[0];
    const int*   ei      = (const int*)d_in[1];
    const float* W       = (const float*)d_in[2];
    const float* att_src = (const float*)d_in[3];
    const float* att_dst = (const float*)d_in[4];
    const float* bias    = (const float*)d_in[5];
    const float* gamma   = (const float*)d_in[6];
    const float* beta    = (const float*)d_in[7];
    float* out = (float*)d_out;

    zero_deg_kernel<<<(NN + 255) / 256, 256>>>();
    count_kernel<<<(ET + 255) / 256, 256>>>(ei);
    scan_kernel<<<1, 1024>>>();
    fill_kernel<<<(ET + 255) / 256, 256>>>(ei);

    dim3 gg((NN + 63) / 64, OUTF / 64);
    gemm_kernel<<<gg, 256>>>(x, W);
    att_kernel<<<NN, 256>>>(att_src, att_dst);

    agg_ln_kernel<<<NN, 256>>>(ei, out, bias, gamma, beta);
}

// round 5
// speedup vs baseline: 1.6135x; 1.1786x over previous
#include <cuda_runtime.h>

#define NN 50000
#define EE 800000
#define ET (EE + NN)          // edges + self-loops = 850000
#define HEADS 8
#define INF 256
#define OUTF 256
#define NEG 0.2f
#define LNEPS 1e-5f
#define SCAN_BLK 1024
#define NSCAN ((NN + SCAN_BLK - 1) / SCAN_BLK)   // 49

typedef unsigned long long ull;

// ---------------- scratch (device globals) -----------------------------------
__device__ float g_h[(size_t)NN * OUTF];        // x @ W  (51.2 MB, L2-resident)
__device__ float g_asrc[NN * HEADS];
__device__ float g_adst[NN * HEADS];
__device__ int   g_deg[NN];
__device__ int   g_start[NN + 1];
__device__ int   g_cursor[NN];
__device__ int   g_part[NSCAN];
__device__ int   g_csr[ET];                     // SRC ids bucketed by dst

// ---------------- GEMM: h = x @ W  (128x128 tile, 8x8 micro, FFMA2) ----------
__global__ void __launch_bounds__(256) gemm_kernel(const float* __restrict__ X,
                                                   const float* __restrict__ W) {
    __shared__ float As[16][132];   // [k][m], transposed A
    __shared__ float Bs[16][132];   // [k][n]

    int tid = threadIdx.x;
    int tx = tid & 15, ty = tid >> 4;
    int row0 = blockIdx.x * 128;
    int col0 = blockIdx.y * 128;

    ull acc[8][4] = {};   // rows: ty*4+{0..3}, 64+ty*4+{0..3}; col pairs: tx*4, +2, 64+tx*4, +66

    for (int k0 = 0; k0 < INF; k0 += 16) {
        #pragma unroll
        for (int i = tid; i < 512; i += 256) {
            int r = i >> 2, q = i & 3;
            float4 v = make_float4(0.f, 0.f, 0.f, 0.f);
            if (row0 + r < NN)
                v = *(const float4*)&X[(size_t)(row0 + r) * INF + k0 + q * 4];
            As[q * 4 + 0][r] = v.x; As[q * 4 + 1][r] = v.y;
            As[q * 4 + 2][r] = v.z; As[q * 4 + 3][r] = v.w;
        }
        #pragma unroll
        for (int i = tid; i < 512; i += 256) {
            int k = i >> 5, nq = i & 31;
            *(float4*)&Bs[k][nq * 4] = *(const float4*)&W[(size_t)(k0 + k) * OUTF + col0 + nq * 4];
        }
        __syncthreads();

        #pragma unroll
        for (int k = 0; k < 16; k++) {
            ull b[4];
            b[0] = *(const ull*)&Bs[k][tx * 4];
            b[1] = *(const ull*)&Bs[k][tx * 4 + 2];
            b[2] = *(const ull*)&Bs[k][tx * 4 + 64];
            b[3] = *(const ull*)&Bs[k][tx * 4 + 66];
            float4 alo = *(const float4*)&As[k][ty * 4];
            float4 ahi = *(const float4*)&As[k][ty * 4 + 64];
            float av[8] = { alo.x, alo.y, alo.z, alo.w, ahi.x, ahi.y, ahi.z, ahi.w };
            #pragma unroll
            for (int mi = 0; mi < 8; mi++) {
                ull ad;
                asm("mov.b64 %0, {%1, %1};" : "=l"(ad) : "f"(av[mi]));
                #pragma unroll
                for (int p = 0; p < 4; p++)
                    asm("fma.rn.f32x2 %0, %1, %2, %0;" : "+l"(acc[mi][p]) : "l"(ad), "l"(b[p]));
            }
        }
        __syncthreads();
    }

    #pragma unroll
    for (int mi = 0; mi < 8; mi++) {
        int r = row0 + (mi < 4 ? ty * 4 + mi : 64 + ty * 4 + mi - 4);
        if (r < NN) {
            float4 lo, hi;
            asm("mov.b64 {%0, %1}, %2;" : "=f"(lo.x), "=f"(lo.y) : "l"(acc[mi][0]));
            asm("mov.b64 {%0, %1}, %2;" : "=f"(lo.z), "=f"(lo.w) : "l"(acc[mi][1]));
            asm("mov.b64 {%0, %1}, %2;" : "=f"(hi.x), "=f"(hi.y) : "l"(acc[mi][2]));
            asm("mov.b64 {%0, %1}, %2;" : "=f"(hi.z), "=f"(hi.w) : "l"(acc[mi][3]));
            *(float4*)&g_h[(size_t)r * OUTF + col0 + tx * 4]      = lo;
            *(float4*)&g_h[(size_t)r * OUTF + col0 + tx * 4 + 64] = hi;
        }
    }
}

// ---------------- per-node attention coefficients ---------------------------
__global__ void att_kernel(const float* __restrict__ att_src,
                           const float* __restrict__ att_dst) {
    int n = blockIdx.x;
    int w = threadIdx.x >> 5, lane = threadIdx.x & 31;   // warp w == head w
    float hv = g_h[(size_t)n * OUTF + w * 32 + lane];
    float s = hv * att_src[w * 32 + lane];
    float d = hv * att_dst[w * 32 + lane];
    #pragma unroll
    for (int o = 16; o; o >>= 1) {
        s += __shfl_down_sync(0xffffffffu, s, o);
        d += __shfl_down_sync(0xffffffffu, d, o);
    }
    if (lane == 0) {
        g_asrc[n * HEADS + w] = s;
        g_adst[n * HEADS + w] = d;
    }
}

// ---------------- CSR build --------------------------------------------------
__global__ void zero_deg_kernel() {
    int i = blockIdx.x * blockDim.x + threadIdx.x;
    if (i < NN) g_deg[i] = 0;
}

__global__ void count_kernel(const int* __restrict__ ei) {
    int e = blockIdx.x * blockDim.x + threadIdx.x;
    if (e >= ET) return;
    int d = (e < EE) ? ei[EE + e] : e - EE;
    atomicAdd(&g_deg[d], 1);
}

// phase 1: per-1024-chunk exclusive scan; chunk totals to g_part
__global__ void scan1_kernel() {
    int tid = threadIdx.x;
    int lane = tid & 31, w = tid >> 5;
    int i = blockIdx.x * SCAN_BLK + tid;
    __shared__ int wsum[32];

    int v = (i < NN) ? g_deg[i] : 0;
    int x = v;
    #pragma unroll
    for (int o = 1; o < 32; o <<= 1) {
        int y = __shfl_up_sync(0xffffffffu, x, o);
        if (lane >= o) x += y;
    }
    if (lane == 31) wsum[w] = x;
    __syncthreads();
    if (w == 0) {
        int y = wsum[lane];
        #pragma unroll
        for (int o = 1; o < 32; o <<= 1) {
            int z = __shfl_up_sync(0xffffffffu, y, o);
            if (lane >= o) y += z;
        }
        wsum[lane] = y;
    }
    __syncthreads();
    int incl = x + (w > 0 ? wsum[w - 1] : 0);
    if (i < NN) g_start[i] = incl - v;        // local exclusive
    if (tid == SCAN_BLK - 1) g_part[blockIdx.x] = incl;
}

// phase 2: exclusive scan of chunk totals (single block)
__global__ void scan2_kernel() {
    int tid = threadIdx.x;                    // 64 threads
    int lane = tid & 31, w = tid >> 5;
    __shared__ int wsum[2];
    int v = (tid < NSCAN) ? g_part[tid] : 0;
    int x = v;
    #pragma unroll
    for (int o = 1; o < 32; o <<= 1) {
        int y = __shfl_up_sync(0xffffffffu, x, o);
        if (lane >= o) x += y;
    }
    if (lane == 31) wsum[w] = x;
    __syncthreads();
    int incl = x + (w > 0 ? wsum[0] : 0);
    if (tid < NSCAN) g_part[tid] = incl - v;  // exclusive
    if (tid == NSCAN - 1) g_start[NN] = incl; // total = ET
}

// phase 3: add chunk offsets, init cursor
__global__ void scan3_kernel() {
    int i = blockIdx.x * blockDim.x + threadIdx.x;
    if (i >= NN) return;
    int s = g_start[i] + g_part[i >> 10];
    g_start[i] = s;
    g_cursor[i] = s;
}

// fill: store SRC node id directly (no later indirection through ei)
__global__ void fill_kernel(const int* __restrict__ ei) {
    int e = blockIdx.x * blockDim.x + threadIdx.x;
    if (e >= ET) return;
    int s, d;
    if (e < EE) { s = ei[e]; d = ei[EE + e]; }
    else        { s = d = e - EE; }
    int pos = atomicAdd(&g_cursor[d], 1);
    g_csr[pos] = s;
}

// ---------------- fused aggregate + softmax + bias + LN + ReLU ---------------
__global__ void agg_ln_kernel(float* __restrict__ out,
                              const float* __restrict__ bias,
                              const float* __restrict__ gamma,
                              const float* __restrict__ beta) {
    int d = blockIdx.x;                 // dst node
    int c = threadIdx.x;                // output column 0..255
    int head = c >> 5, lane = c & 31;

    int beg = g_start[d], end = g_start[d + 1];

    float acc = 0.f, den = 0.f;
    __shared__ int   s_src[64];
    __shared__ float s_ex[64 * HEADS];  // [j][h]

    for (int base = beg; base < end; base += 64) {
        int nb = end - base; if (nb > 64) nb = 64;
        // stage: src ids + all (edge, head) exps, computed once cooperatively
        #pragma unroll
        for (int t = 0; t < 2; t++) {
            int idx = c + t * 256;
            if (idx < nb * HEADS) {
                int j = idx >> 3, h = idx & 7;
                int src = g_csr[base + j];
                if (h == 0) s_src[j] = src;
                float e = g_asrc[src * HEADS + h] + g_adst[d * HEADS + h];
                e = e > 0.f ? e : NEG * e;
                s_ex[idx] = __expf(e);
            }
        }
        __syncthreads();

        int j = 0;
        for (; j + 4 <= nb; j += 4) {
            int s0 = s_src[j], s1 = s_src[j + 1], s2 = s_src[j + 2], s3 = s_src[j + 3];
            float e0 = s_ex[(j    ) * HEADS + head];
            float e1 = s_ex[(j + 1) * HEADS + head];
            float e2 = s_ex[(j + 2) * HEADS + head];
            float e3 = s_ex[(j + 3) * HEADS + head];
            float h0 = g_h[(size_t)s0 * OUTF + c];
            float h1 = g_h[(size_t)s1 * OUTF + c];
            float h2 = g_h[(size_t)s2 * OUTF + c];
            float h3 = g_h[(size_t)s3 * OUTF + c];
            acc += e0 * h0; acc += e1 * h1; acc += e2 * h2; acc += e3 * h3;
            den += e0 + e1 + e2 + e3;
        }
        for (; j < nb; j++) {
            int s0 = s_src[j];
            float e0 = s_ex[j * HEADS + head];
            acc += e0 * g_h[(size_t)s0 * OUTF + c];
            den += e0;
        }
        __syncthreads();
    }

    float v = acc / den + bias[c];      // den > 0 (self-loop guarantees deg>=1)

    // LayerNorm over 256 + ReLU
    __shared__ float ssum[8], ssq[8];
    float s = v, q = v * v;
    #pragma unroll
    for (int o = 16; o; o >>= 1) {
        s += __shfl_down_sync(0xffffffffu, s, o);
        q += __shfl_down_sync(0xffffffffu, q, o);
    }
    if (lane == 0) { ssum[head] = s; ssq[head] = q; }
    __syncthreads();

    __shared__ float mean_s, rstd_s;
    if (c == 0) {
        float S = 0.f, Q = 0.f;
        #pragma unroll
        for (int i = 0; i < 8; i++) { S += ssum[i]; Q += ssq[i]; }
        float mu = S * (1.f / OUTF);
        float var = Q * (1.f / OUTF) - mu * mu;
        mean_s = mu;
        rstd_s = rsqrtf(var + LNEPS);
    }
    __syncthreads();

    float y = (v - mean_s) * rstd_s * gamma[c] + beta[c];
    out[(size_t)d * OUTF + c] = fmaxf(y, 0.f);
}

// ---------------- launch -----------------------------------------------------
extern "C" void kernel_launch(void* const* d_in, const int* in_sizes, int n_in,
                              void* d_out, int out_size) {
    const float* x       = (const float*)d_in[0];
    const int*   ei      = (const int*)d_in[1];
    const float* W       = (const float*)d_in[2];
    const float* att_src = (const float*)d_in[3];
    const float* att_dst = (const float*)d_in[4];
    const float* bias    = (const float*)d_in[5];
    const float* gamma   = (const float*)d_in[6];
    const float* beta    = (const float*)d_in[7];
    float* out = (float*)d_out;

    zero_deg_kernel<<<(NN + 255) / 256, 256>>>();
    count_kernel<<<(ET + 255) / 256, 256>>>(ei);
    scan1_kernel<<<NSCAN, SCAN_BLK>>>();
    scan2_kernel<<<1, 64>>>();
    scan3_kernel<<<(NN + 255) / 256, 256>>>();
    fill_kernel<<<(ET + 255) / 256, 256>>>(ei);

    dim3 gg((NN + 127) / 128, OUTF / 128);
    gemm_kernel<<<gg, 256>>>(x, W);
    att_kernel<<<NN, 256>>>(att_src, att_dst);

    agg_ln_kernel<<<NN, 256>>>(out, bias, gamma, beta);
}

// round 6
// speedup vs baseline: 1.8529x; 1.1484x over previous
#include <cuda_runtime.h>

#define NN 50000
#define EE 800000
#define HEADS 8
#define INF 256
#define OUTF 256
#define NEG 0.2f
#define LNEPS 1e-5f
#define SCAN_BLK 1024
#define NSCAN ((NN + SCAN_BLK - 1) / SCAN_BLK)   // 49

typedef unsigned long long ull;

// ---------------- scratch (device globals) -----------------------------------
__device__ float g_h[(size_t)NN * OUTF];        // x @ W  (51.2 MB, L2-resident)
__device__ float g_asrc[NN * HEADS];
__device__ float g_adst[NN * HEADS];
__device__ int   g_deg[NN];
__device__ int   g_start[NN + 1];
__device__ int   g_cursor[NN];
__device__ int   g_part[NSCAN];
__device__ int   g_csr[EE];                     // SRC ids bucketed by dst (real edges only)

// ---------------- GEMM: h = x @ W  (128x128 tile, 8x8 FFMA2, reg prefetch) ---
__global__ void __launch_bounds__(256) gemm_kernel(const float* __restrict__ X,
                                                   const float* __restrict__ W) {
    __shared__ float As[16][132];   // [k][m], transposed A
    __shared__ float Bs[16][132];   // [k][n]

    int tid = threadIdx.x;
    int tx = tid & 15, ty = tid >> 4;
    int row0 = blockIdx.x * 128;
    int col0 = blockIdx.y * 128;

    int ra0 = tid >> 2,  qa0 = tid & 3;                 // X slot 0
    int ra1 = (tid + 256) >> 2, qa1 = tid & 3;          // X slot 1
    int kb0 = tid >> 5,  nb0 = tid & 31;                // W slot 0
    int kb1 = (tid + 256) >> 5, nb1 = tid & 31;         // W slot 1

    ull acc[8][4] = {};
    float4 xa[2], wb[2];

    // preload k0 = 0
    {
        xa[0] = make_float4(0.f,0.f,0.f,0.f);
        xa[1] = make_float4(0.f,0.f,0.f,0.f);
        if (row0 + ra0 < NN) xa[0] = *(const float4*)&X[(size_t)(row0 + ra0) * INF + qa0 * 4];
        if (row0 + ra1 < NN) xa[1] = *(const float4*)&X[(size_t)(row0 + ra1) * INF + qa1 * 4];
        wb[0] = *(const float4*)&W[(size_t)kb0 * OUTF + col0 + nb0 * 4];
        wb[1] = *(const float4*)&W[(size_t)kb1 * OUTF + col0 + nb1 * 4];
    }

    for (int k0 = 0; k0 < INF; k0 += 16) {
        // stage current tile
        As[qa0 * 4 + 0][ra0] = xa[0].x; As[qa0 * 4 + 1][ra0] = xa[0].y;
        As[qa0 * 4 + 2][ra0] = xa[0].z; As[qa0 * 4 + 3][ra0] = xa[0].w;
        As[qa1 * 4 + 0][ra1] = xa[1].x; As[qa1 * 4 + 1][ra1] = xa[1].y;
        As[qa1 * 4 + 2][ra1] = xa[1].z; As[qa1 * 4 + 3][ra1] = xa[1].w;
        *(float4*)&Bs[kb0][nb0 * 4] = wb[0];
        *(float4*)&Bs[kb1][nb1 * 4] = wb[1];
        __syncthreads();

        // prefetch next tile (overlaps with compute below)
        int kn = k0 + 16;
        if (kn < INF) {
            xa[0] = make_float4(0.f,0.f,0.f,0.f);
            xa[1] = make_float4(0.f,0.f,0.f,0.f);
            if (row0 + ra0 < NN) xa[0] = *(const float4*)&X[(size_t)(row0 + ra0) * INF + kn + qa0 * 4];
            if (row0 + ra1 < NN) xa[1] = *(const float4*)&X[(size_t)(row0 + ra1) * INF + kn + qa1 * 4];
            wb[0] = *(const float4*)&W[(size_t)(kn + kb0) * OUTF + col0 + nb0 * 4];
            wb[1] = *(const float4*)&W[(size_t)(kn + kb1) * OUTF + col0 + nb1 * 4];
        }

        #pragma unroll
        for (int k = 0; k < 16; k++) {
            ull b[4];
            b[0] = *(const ull*)&Bs[k][tx * 4];
            b[1] = *(const ull*)&Bs[k][tx * 4 + 2];
            b[2] = *(const ull*)&Bs[k][tx * 4 + 64];
            b[3] = *(const ull*)&Bs[k][tx * 4 + 66];
            float4 alo = *(const float4*)&As[k][ty * 4];
            float4 ahi = *(const float4*)&As[k][ty * 4 + 64];
            float av[8] = { alo.x, alo.y, alo.z, alo.w, ahi.x, ahi.y, ahi.z, ahi.w };
            #pragma unroll
            for (int mi = 0; mi < 8; mi++) {
                ull ad;
                asm("mov.b64 %0, {%1, %1};" : "=l"(ad) : "f"(av[mi]));
                #pragma unroll
                for (int p = 0; p < 4; p++)
                    asm("fma.rn.f32x2 %0, %1, %2, %0;" : "+l"(acc[mi][p]) : "l"(ad), "l"(b[p]));
            }
        }
        __syncthreads();
    }

    #pragma unroll
    for (int mi = 0; mi < 8; mi++) {
        int r = row0 + (mi < 4 ? ty * 4 + mi : 64 + ty * 4 + mi - 4);
        if (r < NN) {
            float4 lo, hi;
            asm("mov.b64 {%0, %1}, %2;" : "=f"(lo.x), "=f"(lo.y) : "l"(acc[mi][0]));
            asm("mov.b64 {%0, %1}, %2;" : "=f"(lo.z), "=f"(lo.w) : "l"(acc[mi][1]));
            asm("mov.b64 {%0, %1}, %2;" : "=f"(hi.x), "=f"(hi.y) : "l"(acc[mi][2]));
            asm("mov.b64 {%0, %1}, %2;" : "=f"(hi.z), "=f"(hi.w) : "l"(acc[mi][3]));
            *(float4*)&g_h[(size_t)r * OUTF + col0 + tx * 4]      = lo;
            *(float4*)&g_h[(size_t)r * OUTF + col0 + tx * 4 + 64] = hi;
        }
    }
}

// ---------------- per-node attention coefficients ---------------------------
__global__ void att_kernel(const float* __restrict__ att_src,
                           const float* __restrict__ att_dst) {
    int n = blockIdx.x;
    int w = threadIdx.x >> 5, lane = threadIdx.x & 31;   // warp w == head w
    float hv = g_h[(size_t)n * OUTF + w * 32 + lane];
    float s = hv * att_src[w * 32 + lane];
    float d = hv * att_dst[w * 32 + lane];
    #pragma unroll
    for (int o = 16; o; o >>= 1) {
        s += __shfl_down_sync(0xffffffffu, s, o);
        d += __shfl_down_sync(0xffffffffu, d, o);
    }
    if (lane == 0) {
        g_asrc[n * HEADS + w] = s;
        g_adst[n * HEADS + w] = d;
    }
}

// ---------------- CSR build (real edges only; self-loops implicit) ----------
__global__ void zero_deg_kernel() {
    int i = blockIdx.x * blockDim.x + threadIdx.x;
    if (i < NN) g_deg[i] = 0;
}

__global__ void count_kernel(const int* __restrict__ ei) {
    int t = blockIdx.x * blockDim.x + threadIdx.x;
    int e4 = t * 4;
    if (e4 >= EE) return;
    int4 d4 = *(const int4*)&ei[EE + e4];
    atomicAdd(&g_deg[d4.x], 1);
    atomicAdd(&g_deg[d4.y], 1);
    atomicAdd(&g_deg[d4.z], 1);
    atomicAdd(&g_deg[d4.w], 1);
}

// phase 1: per-1024-chunk exclusive scan; chunk totals to g_part
__global__ void scan1_kernel() {
    int tid = threadIdx.x;
    int lane = tid & 31, w = tid >> 5;
    int i = blockIdx.x * SCAN_BLK + tid;
    __shared__ int wsum[32];

    int v = (i < NN) ? g_deg[i] : 0;
    int x = v;
    #pragma unroll
    for (int o = 1; o < 32; o <<= 1) {
        int y = __shfl_up_sync(0xffffffffu, x, o);
        if (lane >= o) x += y;
    }
    if (lane == 31) wsum[w] = x;
    __syncthreads();
    if (w == 0) {
        int y = wsum[lane];
        #pragma unroll
        for (int o = 1; o < 32; o <<= 1) {
            int z = __shfl_up_sync(0xffffffffu, y, o);
            if (lane >= o) y += z;
        }
        wsum[lane] = y;
    }
    __syncthreads();
    int incl = x + (w > 0 ? wsum[w - 1] : 0);
    if (i < NN) g_start[i] = incl - v;        // local exclusive
    if (tid == SCAN_BLK - 1) g_part[blockIdx.x] = incl;
}

// phase 2: exclusive scan of chunk totals (single block)
__global__ void scan2_kernel() {
    int tid = threadIdx.x;                    // 64 threads
    int lane = tid & 31, w = tid >> 5;
    __shared__ int wsum[2];
    int v = (tid < NSCAN) ? g_part[tid] : 0;
    int x = v;
    #pragma unroll
    for (int o = 1; o < 32; o <<= 1) {
        int y = __shfl_up_sync(0xffffffffu, x, o);
        if (lane >= o) x += y;
    }
    if (lane == 31) wsum[w] = x;
    __syncthreads();
    int incl = x + (w > 0 ? wsum[0] : 0);
    if (tid < NSCAN) g_part[tid] = incl - v;  // exclusive
    if (tid == NSCAN - 1) g_start[NN] = incl; // total = EE
}

// phase 3: add chunk offsets, init cursor
__global__ void scan3_kernel() {
    int i = blockIdx.x * blockDim.x + threadIdx.x;
    if (i >= NN) return;
    int s = g_start[i] + g_part[i >> 10];
    g_start[i] = s;
    g_cursor[i] = s;
}

// fill: store SRC node id directly, 4 edges per thread
__global__ void fill_kernel(const int* __restrict__ ei) {
    int t = blockIdx.x * blockDim.x + threadIdx.x;
    int e4 = t * 4;
    if (e4 >= EE) return;
    int4 s4 = *(const int4*)&ei[e4];
    int4 d4 = *(const int4*)&ei[EE + e4];
    g_csr[atomicAdd(&g_cursor[d4.x], 1)] = s4.x;
    g_csr[atomicAdd(&g_cursor[d4.y], 1)] = s4.y;
    g_csr[atomicAdd(&g_cursor[d4.z], 1)] = s4.z;
    g_csr[atomicAdd(&g_cursor[d4.w], 1)] = s4.w;
}

// ---------------- fused aggregate + softmax + bias + LN + ReLU ---------------
__global__ void agg_ln_kernel(float* __restrict__ out,
                              const float* __restrict__ bias,
                              const float* __restrict__ gamma,
                              const float* __restrict__ beta) {
    int d = blockIdx.x;                 // dst node
    int c = threadIdx.x;                // output column 0..255
    int head = c >> 5, lane = c & 31;

    int beg = g_start[d], end = g_start[d + 1];

    // implicit self-loop seeds the accumulators (guarantees den > 0)
    float adst_h = g_adst[d * HEADS + head];
    float es = g_asrc[d * HEADS + head] + adst_h;
    es = es > 0.f ? es : NEG * es;
    float exs = __expf(es);
    float den = exs;
    float acc = exs * g_h[(size_t)d * OUTF + c];

    __shared__ int   s_src[64];
    __shared__ float s_ex[64 * HEADS];  // [j][h]

    for (int base = beg; base < end; base += 64) {
        int nb = end - base; if (nb > 64) nb = 64;
        // stage: src ids + all (edge, head) exps, computed once cooperatively
        #pragma unroll
        for (int t = 0; t < 2; t++) {
            int idx = c + t * 256;
            if (idx < nb * HEADS) {
                int j = idx >> 3, h = idx & 7;
                int src = g_csr[base + j];
                if (h == 0) s_src[j] = src;
                float e = g_asrc[src * HEADS + h] + g_adst[d * HEADS + h];
                e = e > 0.f ? e : NEG * e;
                s_ex[idx] = __expf(e);
            }
        }
        __syncthreads();

        int j = 0;
        for (; j + 8 <= nb; j += 8) {
            int   sj[8]; float ej[8]; float hj[8];
            #pragma unroll
            for (int u = 0; u < 8; u++) {
                sj[u] = s_src[j + u];
                ej[u] = s_ex[(j + u) * HEADS + head];
            }
            #pragma unroll
            for (int u = 0; u < 8; u++)
                hj[u] = g_h[(size_t)sj[u] * OUTF + c];
            #pragma unroll
            for (int u = 0; u < 8; u++) { acc += ej[u] * hj[u]; den += ej[u]; }
        }
        for (; j < nb; j++) {
            int s0 = s_src[j];
            float e0 = s_ex[j * HEADS + head];
            acc += e0 * g_h[(size_t)s0 * OUTF + c];
            den += e0;
        }
        __syncthreads();
    }

    float v = acc / den + bias[c];

    // LayerNorm over 256 + ReLU
    __shared__ float ssum[8], ssq[8];
    float s = v, q = v * v;
    #pragma unroll
    for (int o = 16; o; o >>= 1) {
        s += __shfl_down_sync(0xffffffffu, s, o);
        q += __shfl_down_sync(0xffffffffu, q, o);
    }
    if (lane == 0) { ssum[head] = s; ssq[head] = q; }
    __syncthreads();

    __shared__ float mean_s, rstd_s;
    if (c == 0) {
        float S = 0.f, Q = 0.f;
        #pragma unroll
        for (int i = 0; i < 8; i++) { S += ssum[i]; Q += ssq[i]; }
        float mu = S * (1.f / OUTF);
        float var = Q * (1.f / OUTF) - mu * mu;
        mean_s = mu;
        rstd_s = rsqrtf(var + LNEPS);
    }
    __syncthreads();

    float y = (v - mean_s) * rstd_s * gamma[c] + beta[c];
    out[(size_t)d * OUTF + c] = fmaxf(y, 0.f);
}

// ---------------- launch -----------------------------------------------------
extern "C" void kernel_launch(void* const* d_in, const int* in_sizes, int n_in,
                              void* d_out, int out_size) {
    const float* x       = (const float*)d_in[0];
    const int*   ei      = (const int*)d_in[1];
    const float* W       = (const float*)d_in[2];
    const float* att_src = (const float*)d_in[3];
    const float* att_dst = (const float*)d_in[4];
    const float* bias    = (const float*)d_in[5];
    const float* gamma   = (const float*)d_in[6];
    const float* beta    = (const float*)d_in[7];
    float* out = (float*)d_out;

    zero_deg_kernel<<<(NN + 255) / 256, 256>>>();
    count_kernel<<<(EE / 4 + 255) / 256, 256>>>(ei);
    scan1_kernel<<<NSCAN, SCAN_BLK>>>();
    scan2_kernel<<<1, 64>>>();
    scan3_kernel<<<(NN + 255) / 256, 256>>>();
    fill_kernel<<<(EE / 4 + 255) / 256, 256>>>(ei);

    dim3 gg((NN + 127) / 128, OUTF / 128);
    gemm_kernel<<<gg, 256>>>(x, W);
    att_kernel<<<NN, 256>>>(att_src, att_dst);

    agg_ln_kernel<<<NN, 256>>>(out, bias, gamma, beta);
}

// round 7
// speedup vs baseline: 2.1235x; 1.1460x over previous
#include <cuda_runtime.h>

#define NN 50000
#define EE 800000
#define HEADS 8
#define INF 256
#define OUTF 256
#define NEG 0.2f
#define LNEPS 1e-5f
#define SCAN_BLK 1024
#define NSCAN ((NN + SCAN_BLK - 1) / SCAN_BLK)   // 49

typedef unsigned long long ull;

// ---------------- scratch (device globals) -----------------------------------
__device__ float g_h[(size_t)NN * OUTF];        // x @ W  (51.2 MB, L2-resident)
__device__ float g_asrc[NN * HEADS];
__device__ float g_adst[NN * HEADS];
__device__ int   g_deg[NN];
__device__ int   g_start[NN + 1];
__device__ int   g_cursor[NN];
__device__ int   g_part[NSCAN];
__device__ int   g_csr[EE];                     // SRC ids bucketed by dst (real edges only)

// ---------------- prep: zero deg + attention accumulators --------------------
__global__ void prep_zero_kernel() {
    int i = blockIdx.x * blockDim.x + threadIdx.x;
    if (i < NN * HEADS) { g_asrc[i] = 0.f; g_adst[i] = 0.f; }
    if (i < NN) g_deg[i] = 0;
}

// ---------------- GEMM: h = x @ W + fused att partial reduction --------------
__global__ void __launch_bounds__(256) gemm_kernel(const float* __restrict__ X,
                                                   const float* __restrict__ W,
                                                   const float* __restrict__ att_src,
                                                   const float* __restrict__ att_dst) {
    __shared__ float As[16][132];   // [k][m], transposed A
    __shared__ float Bs[16][132];   // [k][n]

    int tid = threadIdx.x;
    int tx = tid & 15, ty = tid >> 4;
    int row0 = blockIdx.x * 128;
    int col0 = blockIdx.y * 128;

    int ra0 = tid >> 2,  qa0 = tid & 3;                 // X slot 0
    int ra1 = (tid + 256) >> 2, qa1 = tid & 3;          // X slot 1
    int kb0 = tid >> 5,  nb0 = tid & 31;                // W slot 0
    int kb1 = (tid + 256) >> 5, nb1 = tid & 31;         // W slot 1

    ull acc[8][4] = {};
    float4 xa[2], wb[2];

    // preload k0 = 0
    {
        xa[0] = make_float4(0.f,0.f,0.f,0.f);
        xa[1] = make_float4(0.f,0.f,0.f,0.f);
        if (row0 + ra0 < NN) xa[0] = *(const float4*)&X[(size_t)(row0 + ra0) * INF + qa0 * 4];
        if (row0 + ra1 < NN) xa[1] = *(const float4*)&X[(size_t)(row0 + ra1) * INF + qa1 * 4];
        wb[0] = *(const float4*)&W[(size_t)kb0 * OUTF + col0 + nb0 * 4];
        wb[1] = *(const float4*)&W[(size_t)kb1 * OUTF + col0 + nb1 * 4];
    }

    for (int k0 = 0; k0 < INF; k0 += 16) {
        As[qa0 * 4 + 0][ra0] = xa[0].x; As[qa0 * 4 + 1][ra0] = xa[0].y;
        As[qa0 * 4 + 2][ra0] = xa[0].z; As[qa0 * 4 + 3][ra0] = xa[0].w;
        As[qa1 * 4 + 0][ra1] = xa[1].x; As[qa1 * 4 + 1][ra1] = xa[1].y;
        As[qa1 * 4 + 2][ra1] = xa[1].z; As[qa1 * 4 + 3][ra1] = xa[1].w;
        *(float4*)&Bs[kb0][nb0 * 4] = wb[0];
        *(float4*)&Bs[kb1][nb1 * 4] = wb[1];
        __syncthreads();

        int kn = k0 + 16;
        if (kn < INF) {
            xa[0] = make_float4(0.f,0.f,0.f,0.f);
            xa[1] = make_float4(0.f,0.f,0.f,0.f);
            if (row0 + ra0 < NN) xa[0] = *(const float4*)&X[(size_t)(row0 + ra0) * INF + kn + qa0 * 4];
            if (row0 + ra1 < NN) xa[1] = *(const float4*)&X[(size_t)(row0 + ra1) * INF + kn + qa1 * 4];
            wb[0] = *(const float4*)&W[(size_t)(kn + kb0) * OUTF + col0 + nb0 * 4];
            wb[1] = *(const float4*)&W[(size_t)(kn + kb1) * OUTF + col0 + nb1 * 4];
        }

        #pragma unroll
        for (int k = 0; k < 16; k++) {
            ull b[4];
            b[0] = *(const ull*)&Bs[k][tx * 4];
            b[1] = *(const ull*)&Bs[k][tx * 4 + 2];
            b[2] = *(const ull*)&Bs[k][tx * 4 + 64];
            b[3] = *(const ull*)&Bs[k][tx * 4 + 66];
            float4 alo = *(const float4*)&As[k][ty * 4];
            float4 ahi = *(const float4*)&As[k][ty * 4 + 64];
            float av[8] = { alo.x, alo.y, alo.z, alo.w, ahi.x, ahi.y, ahi.z, ahi.w };
            #pragma unroll
            for (int mi = 0; mi < 8; mi++) {
                ull ad;
                asm("mov.b64 %0, {%1, %1};" : "=l"(ad) : "f"(av[mi]));
                #pragma unroll
                for (int p = 0; p < 4; p++)
                    asm("fma.rn.f32x2 %0, %1, %2, %0;" : "+l"(acc[mi][p]) : "l"(ad), "l"(b[p]));
            }
        }
        __syncthreads();
    }

    // att vectors for this thread's 8 columns
    float4 as0 = *(const float4*)&att_src[col0 + tx * 4];
    float4 as1 = *(const float4*)&att_src[col0 + tx * 4 + 64];
    float4 ad0 = *(const float4*)&att_dst[col0 + tx * 4];
    float4 ad1 = *(const float4*)&att_dst[col0 + tx * 4 + 64];
    int head_lo = (col0 >> 5) + (tx >> 3);
    int head_hi = head_lo + 2;

    #pragma unroll
    for (int mi = 0; mi < 8; mi++) {
        int r = row0 + (mi < 4 ? ty * 4 + mi : 64 + ty * 4 + mi - 4);
        float4 lo, hi;
        asm("mov.b64 {%0, %1}, %2;" : "=f"(lo.x), "=f"(lo.y) : "l"(acc[mi][0]));
        asm("mov.b64 {%0, %1}, %2;" : "=f"(lo.z), "=f"(lo.w) : "l"(acc[mi][1]));
        asm("mov.b64 {%0, %1}, %2;" : "=f"(hi.x), "=f"(hi.y) : "l"(acc[mi][2]));
        asm("mov.b64 {%0, %1}, %2;" : "=f"(hi.z), "=f"(hi.w) : "l"(acc[mi][3]));

        // partial att dots over this thread's 4-col groups (one head each)
        float ps = lo.x * as0.x + lo.y * as0.y + lo.z * as0.z + lo.w * as0.w;
        float ph = hi.x * as1.x + hi.y * as1.y + hi.z * as1.z + hi.w * as1.w;
        float ds = lo.x * ad0.x + lo.y * ad0.y + lo.z * ad0.z + lo.w * ad0.w;
        float dh = hi.x * ad1.x + hi.y * ad1.y + hi.z * ad1.z + hi.w * ad1.w;
        // reduce across the 8 tx-lanes sharing a head (xor 1,2,4 stays in group)
        #pragma unroll
        for (int o = 1; o <= 4; o <<= 1) {
            ps += __shfl_xor_sync(0xffffffffu, ps, o);
            ph += __shfl_xor_sync(0xffffffffu, ph, o);
            ds += __shfl_xor_sync(0xffffffffu, ds, o);
            dh += __shfl_xor_sync(0xffffffffu, dh, o);
        }

        if (r < NN) {
            *(float4*)&g_h[(size_t)r * OUTF + col0 + tx * 4]      = lo;
            *(float4*)&g_h[(size_t)r * OUTF + col0 + tx * 4 + 64] = hi;
            if ((tx & 7) == 0) {
                atomicAdd(&g_asrc[r * HEADS + head_lo], ps);
                atomicAdd(&g_asrc[r * HEADS + head_hi], ph);
                atomicAdd(&g_adst[r * HEADS + head_lo], ds);
                atomicAdd(&g_adst[r * HEADS + head_hi], dh);
            }
        }
    }
}

// ---------------- CSR build (real edges only; self-loops implicit) ----------
__global__ void count_kernel(const int* __restrict__ ei) {
    int t = blockIdx.x * blockDim.x + threadIdx.x;
    int e4 = t * 4;
    if (e4 >= EE) return;
    int4 d4 = *(const int4*)&ei[EE + e4];
    atomicAdd(&g_deg[d4.x], 1);
    atomicAdd(&g_deg[d4.y], 1);
    atomicAdd(&g_deg[d4.z], 1);
    atomicAdd(&g_deg[d4.w], 1);
}

__global__ void scan1_kernel() {
    int tid = threadIdx.x;
    int lane = tid & 31, w = tid >> 5;
    int i = blockIdx.x * SCAN_BLK + tid;
    __shared__ int wsum[32];

    int v = (i < NN) ? g_deg[i] : 0;
    int x = v;
    #pragma unroll
    for (int o = 1; o < 32; o <<= 1) {
        int y = __shfl_up_sync(0xffffffffu, x, o);
        if (lane >= o) x += y;
    }
    if (lane == 31) wsum[w] = x;
    __syncthreads();
    if (w == 0) {
        int y = wsum[lane];
        #pragma unroll
        for (int o = 1; o < 32; o <<= 1) {
            int z = __shfl_up_sync(0xffffffffu, y, o);
            if (lane >= o) y += z;
        }
        wsum[lane] = y;
    }
    __syncthreads();
    int incl = x + (w > 0 ? wsum[w - 1] : 0);
    if (i < NN) g_start[i] = incl - v;        // local exclusive
    if (tid == SCAN_BLK - 1) g_part[blockIdx.x] = incl;
}

__global__ void scan2_kernel() {
    int tid = threadIdx.x;                    // 64 threads
    int lane = tid & 31, w = tid >> 5;
    __shared__ int wsum[2];
    int v = (tid < NSCAN) ? g_part[tid] : 0;
    int x = v;
    #pragma unroll
    for (int o = 1; o < 32; o <<= 1) {
        int y = __shfl_up_sync(0xffffffffu, x, o);
        if (lane >= o) x += y;
    }
    if (lane == 31) wsum[w] = x;
    __syncthreads();
    int incl = x + (w > 0 ? wsum[0] : 0);
    if (tid < NSCAN) g_part[tid] = incl - v;  // exclusive
    if (tid == NSCAN - 1) g_start[NN] = incl; // total = EE
}

__global__ void scan3_kernel() {
    int i = blockIdx.x * blockDim.x + threadIdx.x;
    if (i >= NN) return;
    int s = g_start[i] + g_part[i >> 10];
    g_start[i] = s;
    g_cursor[i] = s;
}

__global__ void fill_kernel(const int* __restrict__ ei) {
    int t = blockIdx.x * blockDim.x + threadIdx.x;
    int e4 = t * 4;
    if (e4 >= EE) return;
    int4 s4 = *(const int4*)&ei[e4];
    int4 d4 = *(const int4*)&ei[EE + e4];
    g_csr[atomicAdd(&g_cursor[d4.x], 1)] = s4.x;
    g_csr[atomicAdd(&g_cursor[d4.y], 1)] = s4.y;
    g_csr[atomicAdd(&g_cursor[d4.z], 1)] = s4.z;
    g_csr[atomicAdd(&g_cursor[d4.w], 1)] = s4.w;
}

// ---------------- fused aggregate + softmax + bias + LN + ReLU ---------------
__global__ void agg_ln_kernel(float* __restrict__ out,
                              const float* __restrict__ bias,
                              const float* __restrict__ gamma,
                              const float* __restrict__ beta) {
    int d = blockIdx.x;                 // dst node
    int c = threadIdx.x;                // output column 0..255
    int head = c >> 5, lane = c & 31;

    int beg = g_start[d], end = g_start[d + 1];

    // implicit self-loop seeds the accumulators (guarantees den > 0)
    float adst_h = g_adst[d * HEADS + head];
    float es = g_asrc[d * HEADS + head] + adst_h;
    es = es > 0.f ? es : NEG * es;
    float exs = __expf(es);
    float den = exs;
    float acc = exs * __ldg(&g_h[(size_t)d * OUTF + c]);

    __shared__ int   s_src[64];
    __shared__ float s_ex[64 * HEADS];  // [j][h]

    for (int base = beg; base < end; base += 64) {
        int nb = end - base; if (nb > 64) nb = 64;
        #pragma unroll
        for (int t = 0; t < 2; t++) {
            int idx = c + t * 256;
            if (idx < nb * HEADS) {
                int j = idx >> 3, h = idx & 7;
                int src = g_csr[base + j];
                if (h == 0) s_src[j] = src;
                float e = g_asrc[src * HEADS + h] + g_adst[d * HEADS + h];
                e = e > 0.f ? e : NEG * e;
                s_ex[idx] = __expf(e);
            }
        }
        __syncthreads();

        int j = 0;
        for (; j + 8 <= nb; j += 8) {
            int   sj[8]; float ej[8]; float hj[8];
            #pragma unroll
            for (int u = 0; u < 8; u++) {
                sj[u] = s_src[j + u];
                ej[u] = s_ex[(j + u) * HEADS + head];
            }
            #pragma unroll
            for (int u = 0; u < 8; u++)
                hj[u] = __ldg(&g_h[(size_t)sj[u] * OUTF + c]);
            #pragma unroll
            for (int u = 0; u < 8; u++) { acc += ej[u] * hj[u]; den += ej[u]; }
        }
        for (; j < nb; j++) {
            int s0 = s_src[j];
            float e0 = s_ex[j * HEADS + head];
            acc += e0 * __ldg(&g_h[(size_t)s0 * OUTF + c]);
            den += e0;
        }
        __syncthreads();
    }

    float v = acc / den + bias[c];

    __shared__ float ssum[8], ssq[8];
    float s = v, q = v * v;
    #pragma unroll
    for (int o = 16; o; o >>= 1) {
        s += __shfl_down_sync(0xffffffffu, s, o);
        q += __shfl_down_sync(0xffffffffu, q, o);
    }
    if (lane == 0) { ssum[head] = s; ssq[head] = q; }
    __syncthreads();

    __shared__ float mean_s, rstd_s;
    if (c == 0) {
        float S = 0.f, Q = 0.f;
        #pragma unroll
        for (int i = 0; i < 8; i++) { S += ssum[i]; Q += ssq[i]; }
        float mu = S * (1.f / OUTF);
        float var = Q * (1.f / OUTF) - mu * mu;
        mean_s = mu;
        rstd_s = rsqrtf(var + LNEPS);
    }
    __syncthreads();

    float y = (v - mean_s) * rstd_s * gamma[c] + beta[c];
    out[(size_t)d * OUTF + c] = fmaxf(y, 0.f);
}

// ---------------- launch (fork-join: CSR build overlaps GEMM) ----------------
static cudaStream_t g_s2 = 0;
static cudaEvent_t  g_evA = 0, g_evB = 0;

extern "C" void kernel_launch(void* const* d_in, const int* in_sizes, int n_in,
                              void* d_out, int out_size) {
    const float* x       = (const float*)d_in[0];
    const int*   ei      = (const int*)d_in[1];
    const float* W       = (const float*)d_in[2];
    const float* att_src = (const float*)d_in[3];
    const float* att_dst = (const float*)d_in[4];
    const float* bias    = (const float*)d_in[5];
    const float* gamma   = (const float*)d_in[6];
    const float* beta    = (const float*)d_in[7];
    float* out = (float*)d_out;

    if (!g_s2) {   // host-side resources only; created on the uncaptured first call
        cudaStreamCreateWithFlags(&g_s2, cudaStreamNonBlocking);
        cudaEventCreateWithFlags(&g_evA, cudaEventDisableTiming);
        cudaEventCreateWithFlags(&g_evB, cudaEventDisableTiming);
    }

    // main stream: prep zero (needed by both branches)
    prep_zero_kernel<<<(NN * HEADS + 255) / 256, 256>>>();
    cudaEventRecord(g_evA, 0);

    // side stream: CSR build (depends only on edge_index)
    cudaStreamWaitEvent(g_s2, g_evA, 0);
    count_kernel<<<(EE / 4 + 255) / 256, 256, 0, g_s2>>>(ei);
    scan1_kernel<<<NSCAN, SCAN_BLK, 0, g_s2>>>();
    scan2_kernel<<<1, 64, 0, g_s2>>>();
    scan3_kernel<<<(NN + 255) / 256, 256, 0, g_s2>>>();
    fill_kernel<<<(EE / 4 + 255) / 256, 256, 0, g_s2>>>(ei);
    cudaEventRecord(g_evB, g_s2);

    // main stream: GEMM + fused att (overlaps with CSR build)
    dim3 gg((NN + 127) / 128, OUTF / 128);
    gemm_kernel<<<gg, 256>>>(x, W, att_src, att_dst);

    // join, then fused aggregate+softmax+LN
    cudaStreamWaitEvent(0, g_evB, 0);
    agg_ln_kernel<<<NN, 256>>>(out, bias, gamma, beta);
}